// round 15
// baseline (speedup 1.0000x reference)
#include <cuda_runtime.h>
#include <cuda_bf16.h>
#include <cuda_fp16.h>
#include <cstdint>

constexpr int B = 4;
constexpr int S = 4096;
constexpr int D = 256;
constexpr int L = 8921;

constexpr int NST = 16;     // S/256 s-tiles in K1
constexpr int NLT = 70;     // ceil(L/128)

// ---------------- device scratch ------------------------------------------
__device__ float g_pm[(size_t)B * L * NST];
__device__ float g_pz[(size_t)B * L * NST];
__device__ float g_sf[(size_t)B * L * NST];   // per-(row,tile) alpha scale

__device__ __align__(128) __nv_bfloat16 gUh[(size_t)L * D];   // U*log2e hi
__device__ __align__(128) __nv_bfloat16 gUl[(size_t)L * D];   // U*log2e lo
__device__ __align__(128) __nv_bfloat16 gXh[(size_t)B * S * D];
__device__ __align__(128) __nv_bfloat16 gXl[(size_t)B * S * D];
__device__ __align__(128) __half        gVh[(size_t)B * D * S];  // x^T fp16 hi
__device__ __align__(128) __half        gVl[(size_t)B * D * S];  // x^T fp16 lo

// ---------------- helpers --------------------------------------------------
__device__ __forceinline__ uint32_t smem_u32(const void* p) {
    uint32_t a;
    asm("{ .reg .u64 t; cvta.to.shared.u64 t, %1; cvt.u32.u64 %0, t; }" : "=r"(a) : "l"(p));
    return a;
}
__device__ __forceinline__ void bulk_cp(uint32_t dst, const void* src, uint32_t bytes, uint32_t mb) {
    asm volatile("cp.async.bulk.shared::cluster.global.mbarrier::complete_tx::bytes "
                 "[%0], [%1], %2, [%3];"
                 :: "r"(dst), "l"(src), "r"(bytes), "r"(mb) : "memory");
}
__device__ __forceinline__ void mbar_init(uint32_t a, uint32_t n) {
    asm volatile("mbarrier.init.shared.b64 [%0], %1;" :: "r"(a), "r"(n) : "memory");
}
__device__ __forceinline__ void mbar_arrive_tx(uint32_t a, uint32_t bytes) {
    asm volatile("mbarrier.arrive.expect_tx.shared.b64 _, [%0], %1;"
                 :: "r"(a), "r"(bytes) : "memory");
}
__device__ __forceinline__ void mbar_wait(uint32_t a, uint32_t parity) {
    asm volatile(
        "{\n\t.reg .pred P;\n\t"
        "WL%=:\n\t"
        "mbarrier.try_wait.parity.acquire.cta.shared::cta.b64 P, [%0], %1, 0x989680;\n\t"
        "@P bra WD%=;\n\t"
        "bra WL%=;\n\t"
        "WD%=:\n\t}"
        :: "r"(a), "r"(parity) : "memory");
}
__device__ __forceinline__ void ldsm4(uint32_t* r, uint32_t a) {
    asm volatile("ldmatrix.sync.aligned.m8n8.x4.shared.b16 {%0,%1,%2,%3}, [%4];"
                 : "=r"(r[0]), "=r"(r[1]), "=r"(r[2]), "=r"(r[3]) : "r"(a));
}
__device__ __forceinline__ void mma_bf16(float* d, const uint32_t* a, uint32_t b0, uint32_t b1) {
    asm volatile("mma.sync.aligned.m16n8k16.row.col.f32.bf16.bf16.f32 "
                 "{%0,%1,%2,%3}, {%4,%5,%6,%7}, {%8,%9}, {%0,%1,%2,%3};"
                 : "+f"(d[0]), "+f"(d[1]), "+f"(d[2]), "+f"(d[3])
                 : "r"(a[0]), "r"(a[1]), "r"(a[2]), "r"(a[3]), "r"(b0), "r"(b1));
}
__device__ __forceinline__ void mma_f16(float* d, const uint32_t* a, uint32_t b0, uint32_t b1) {
    asm volatile("mma.sync.aligned.m16n8k16.row.col.f32.f16.f16.f32 "
                 "{%0,%1,%2,%3}, {%4,%5,%6,%7}, {%8,%9}, {%0,%1,%2,%3};"
                 : "+f"(d[0]), "+f"(d[1]), "+f"(d[2]), "+f"(d[3])
                 : "r"(a[0]), "r"(a[1]), "r"(a[2]), "r"(a[3]), "r"(b0), "r"(b1));
}
__device__ __forceinline__ float ex2f(float x) {
    float y;
    asm("ex2.approx.f32 %0, %1;" : "=f"(y) : "f"(x));
    return y;
}
__device__ __forceinline__ void split1(float v, __nv_bfloat16& h, __nv_bfloat16& l) {
    h = __float2bfloat16(v);
    l = __float2bfloat16(v - __bfloat162float(h));
}
__device__ __forceinline__ uint32_t pack2(__nv_bfloat16 a, __nv_bfloat16 b) {
    __nv_bfloat162 t = __halves2bfloat162(a, b);
    return *reinterpret_cast<uint32_t*>(&t);
}
__device__ __forceinline__ uint32_t packh2(float a, float b) {
    __half2 t = __floats2half2_rn(a, b);
    return *reinterpret_cast<uint32_t*>(&t);
}

// ---------------- smem layouts ----------------------------------------------
// k-chunk 64 (128B rows), pitch 144 (conflict-free ldsm, 16B aligned)
constexpr int PITCH  = 144;
// K1
constexpr int ST_AH  = 0;                    // 128*144
constexpr int ST_AL  = 18432;
constexpr int ST_BH  = 36864;                // 256*144
constexpr int ST_BL  = 73728;
constexpr int STAGE1 = 110592;
constexpr int STATS1 = 2 * STAGE1;           // 221184; stats 4608B
constexpr int MB1    = STATS1 + 4864;        // 226048
constexpr int SMEM1  = 226304;
// K3
constexpr int S3_A   = 0;                    // 128*144
constexpr int S3_BH  = 18432;                // 256*144
constexpr int S3_BL  = 55296;
constexpr int STAGE3 = 92160;
constexpr int SFS3   = 2 * STAGE3;           // 184320; sfs 8192B
constexpr int MB3    = SFS3 + 8192;          // 192512
constexpr int SMEM3  = 192768;

constexpr int LDC = 264;   // epilogue staging row stride (fp32)

// ---------------- precompute kernels ---------------------------------------
__global__ void k_split_u(const float* __restrict__ src) {
    int i = blockIdx.x * blockDim.x + threadIdx.x;
    if (i >= L * D / 4) return;
    float4 v = ((const float4*)src)[i];
    const float LOG2E = 1.4426950408889634f;
    v.x *= LOG2E; v.y *= LOG2E; v.z *= LOG2E; v.w *= LOG2E;
    __nv_bfloat16 h0,h1,h2,h3,l0,l1,l2,l3;
    split1(v.x,h0,l0); split1(v.y,h1,l1); split1(v.z,h2,l2); split1(v.w,h3,l3);
    ((uint2*)gUh)[i] = make_uint2(pack2(h0,h1), pack2(h2,h3));
    ((uint2*)gUl)[i] = make_uint2(pack2(l0,l1), pack2(l2,l3));
}
// one pass over x: bf16 split (natural, for K1) + fp16 split (transposed, for K3)
__global__ void k_tsplit(const float* __restrict__ x) {
    __shared__ float t[32][33];
    int b = blockIdx.z, s0 = blockIdx.x * 32, d0 = blockIdx.y * 32;
    int tx = threadIdx.x, ty = threadIdx.y;
    const float* xb = x + (size_t)b * S * D;
#pragma unroll
    for (int i = 0; i < 32; i += 8) {
        float v = xb[(size_t)(s0 + ty + i) * D + d0 + tx];
        t[ty + i][tx] = v;
        __nv_bfloat16 h, l; split1(v, h, l);
        size_t o = ((size_t)b * S + s0 + ty + i) * D + d0 + tx;
        gXh[o] = h; gXl[o] = l;
    }
    __syncthreads();
#pragma unroll
    for (int i = 0; i < 32; i += 8) {
        int dr = ty + i;
        float v = t[tx][dr];
        __half h = __float2half(v);
        __half l = __float2half(v - __half2float(h));
        size_t o = ((size_t)b * D + d0 + dr) * S + s0 + tx;
        gVh[o] = h; gVl[o] = l;
    }
}

// ---------------- MMA fragment context --------------------------------------
struct MmaCtx { uint32_t arow, brow; };
__device__ __forceinline__ MmaCtx make_ctx(int warp, int lane) {
    int wm = warp & 3, wn = warp >> 2;
    MmaCtx c;
    c.arow = (uint32_t)((wm * 32 + (lane & 15)) * PITCH + (lane >> 4) * 16);
    c.brow = (uint32_t)((wn * 64 + (lane & 7) + ((lane >> 4) & 1) * 8) * PITCH
                        + ((lane >> 3) & 1) * 16);
    return c;
}

// K1 body: bf16 3-term, k64 (4x k16), term-outermost
__device__ __forceinline__ void tile_mma1(uint32_t base, const MmaCtx& cx,
                                          float (&acc)[2][8][4])
{
#pragma unroll
    for (int ks = 0; ks < 4; ks++) {
        uint32_t Ah[2][4], Al[2][4];
#pragma unroll
        for (int mt = 0; mt < 2; mt++) {
            ldsm4(Ah[mt], base + ST_AH + cx.arow + mt * (16 * PITCH) + ks * 32);
            ldsm4(Al[mt], base + ST_AL + cx.arow + mt * (16 * PITCH) + ks * 32);
        }
#pragma unroll
        for (int nph = 0; nph < 2; nph++) {
            uint32_t Bh[2][4], Bl[2][4];
#pragma unroll
            for (int j = 0; j < 2; j++) {
                int np = nph * 2 + j;
                ldsm4(Bh[j], base + ST_BH + cx.brow + np * (16 * PITCH) + ks * 32);
                ldsm4(Bl[j], base + ST_BL + cx.brow + np * (16 * PITCH) + ks * 32);
            }
#pragma unroll
            for (int j = 0; j < 2; j++) {
                int np = nph * 2 + j;
#pragma unroll
                for (int mt = 0; mt < 2; mt++) {
                    mma_bf16(acc[mt][np*2],   Ah[mt], Bh[j][0], Bh[j][1]);
                    mma_bf16(acc[mt][np*2+1], Ah[mt], Bh[j][2], Bh[j][3]);
                }
            }
#pragma unroll
            for (int j = 0; j < 2; j++) {
                int np = nph * 2 + j;
#pragma unroll
                for (int mt = 0; mt < 2; mt++) {
                    mma_bf16(acc[mt][np*2],   Ah[mt], Bl[j][0], Bl[j][1]);
                    mma_bf16(acc[mt][np*2+1], Ah[mt], Bl[j][2], Bl[j][3]);
                }
            }
#pragma unroll
            for (int j = 0; j < 2; j++) {
                int np = nph * 2 + j;
#pragma unroll
                for (int mt = 0; mt < 2; mt++) {
                    mma_bf16(acc[mt][np*2],   Al[mt], Bh[j][0], Bh[j][1]);
                    mma_bf16(acc[mt][np*2+1], Al[mt], Bh[j][2], Bh[j][3]);
                }
            }
        }
    }
}

// K3 body: fp16 2-term, k64
__device__ __forceinline__ void tile_mma3(uint32_t base, const MmaCtx& cx,
                                          float (&acc)[2][8][4])
{
#pragma unroll
    for (int ks = 0; ks < 4; ks++) {
        uint32_t Ah[2][4];
#pragma unroll
        for (int mt = 0; mt < 2; mt++)
            ldsm4(Ah[mt], base + S3_A + cx.arow + mt * (16 * PITCH) + ks * 32);
#pragma unroll
        for (int nph = 0; nph < 2; nph++) {
            uint32_t Bh[2][4], Bl[2][4];
#pragma unroll
            for (int j = 0; j < 2; j++) {
                int np = nph * 2 + j;
                ldsm4(Bh[j], base + S3_BH + cx.brow + np * (16 * PITCH) + ks * 32);
                ldsm4(Bl[j], base + S3_BL + cx.brow + np * (16 * PITCH) + ks * 32);
            }
#pragma unroll
            for (int j = 0; j < 2; j++) {
                int np = nph * 2 + j;
#pragma unroll
                for (int mt = 0; mt < 2; mt++) {
                    mma_f16(acc[mt][np*2],   Ah[mt], Bh[j][0], Bh[j][1]);
                    mma_f16(acc[mt][np*2+1], Ah[mt], Bh[j][2], Bh[j][3]);
                }
            }
#pragma unroll
            for (int j = 0; j < 2; j++) {
                int np = nph * 2 + j;
#pragma unroll
                for (int mt = 0; mt < 2; mt++) {
                    mma_f16(acc[mt][np*2],   Ah[mt], Bl[j][0], Bl[j][1]);
                    mma_f16(acc[mt][np*2+1], Ah[mt], Bl[j][2], Bl[j][3]);
                }
            }
        }
    }
}

// ---------------- K1: e_val = 2^(s'-m_tile) + per-tile stats ----------------
__global__ void __launch_bounds__(512) k1(float* __restrict__ ev)
{
    extern __shared__ __align__(128) char smem[];
    const uint32_t sb = smem_u32(smem);
    const int tid = threadIdx.x, lane = tid & 31, warp = tid >> 5;
    const int wm = warp & 3, wn = warp >> 2;
    const int bb = blockIdx.z, lt = blockIdx.y, st = blockIdx.x;
    const int l0 = lt * 128, s0 = st * 256;
    const MmaCtx cx = make_ctx(warp, lane);
    const int nA = max(0, min(128, L - l0));   // valid A rows

    if (tid == 0) { mbar_init(sb + MB1, 1); mbar_init(sb + MB1 + 8, 1); }
    __syncthreads();

    float acc[2][8][4];
#pragma unroll
    for (int i = 0; i < 2; i++)
#pragma unroll
        for (int j = 0; j < 8; j++)
#pragma unroll
            for (int k = 0; k < 4; k++) acc[i][j][k] = 0.f;

    auto issue = [&](int c) {
        const uint32_t mb   = sb + MB1 + (c & 1) * 8;
        const uint32_t base = sb + (c & 1) * STAGE1;
        const int kc = c * 64;
        if (tid == 0)
            mbar_arrive_tx(mb, (uint32_t)(512 + 2 * nA) * 128u);
        if (tid < 256) {
            // B rows (x): hi and lo
            bulk_cp(base + ST_BH + tid * PITCH,
                    gXh + ((size_t)bb * S + s0 + tid) * D + kc, 128, mb);
            bulk_cp(base + ST_BL + tid * PITCH,
                    gXl + ((size_t)bb * S + s0 + tid) * D + kc, 128, mb);
        } else {
            int r = tid & 127;
            if (r < nA) {
                if (tid < 384)
                    bulk_cp(base + ST_AH + r * PITCH,
                            gUh + (size_t)(l0 + r) * D + kc, 128, mb);
                else
                    bulk_cp(base + ST_AL + r * PITCH,
                            gUl + (size_t)(l0 + r) * D + kc, 128, mb);
            }
        }
    };

    issue(0);
    issue(1);

    for (int c = 0; c < 4; c++) {
        mbar_wait(sb + MB1 + (c & 1) * 8, (c >> 1) & 1);
        tile_mma1(sb + (c & 1) * STAGE1, cx, acc);
        __syncthreads();
        if (c + 2 < 4) issue(c + 2);
    }

    // ---- epilogue (log2 domain): tile max, e-values, z, stores ----
    float* spmax = (float*)(smem + STATS1);   // [4][128]
    float* spz   = spmax + 512;               // [4][128]
    float* srow  = spz + 512;                 // [128]
    float* Cs    = (float*)smem;              // [128][LDC]
    const int rbase = wm * 32 + (lane >> 2);

#pragma unroll
    for (int mt = 0; mt < 2; mt++)
#pragma unroll
        for (int h = 0; h < 2; h++) {
            float m = -3.4e38f;
#pragma unroll
            for (int nt = 0; nt < 8; nt++)
                m = fmaxf(m, fmaxf(acc[mt][nt][h*2], acc[mt][nt][h*2+1]));
            m = fmaxf(m, __shfl_xor_sync(0xffffffffu, m, 1));
            m = fmaxf(m, __shfl_xor_sync(0xffffffffu, m, 2));
            if ((lane & 3) == 0)
                spmax[wn * 128 + rbase + mt * 16 + h * 8] = m;
        }
    __syncthreads();
    if (tid < 128) {
        float m = fmaxf(fmaxf(spmax[tid], spmax[128 + tid]),
                        fmaxf(spmax[256 + tid], spmax[384 + tid]));
        srow[tid] = m;
    }
    __syncthreads();
#pragma unroll
    for (int mt = 0; mt < 2; mt++) {
        const int r = wm * 32 + mt * 16 + (lane >> 2);
        const int ccol = wn * 64 + (lane & 3) * 2;
#pragma unroll
        for (int h = 0; h < 2; h++) {
            float M = srow[rbase + mt * 16 + h * 8];
            float z = 0.f;
            float e0[8], e1[8];
#pragma unroll
            for (int nt = 0; nt < 8; nt++) {
                e0[nt] = ex2f(acc[mt][nt][h*2]     - M);
                e1[nt] = ex2f(acc[mt][nt][h*2 + 1] - M);
                z += e0[nt] + e1[nt];
            }
            z += __shfl_xor_sync(0xffffffffu, z, 1);
            z += __shfl_xor_sync(0xffffffffu, z, 2);
            if ((lane & 3) == 0)
                spz[wn * 128 + rbase + mt * 16 + h * 8] = z;
#pragma unroll
            for (int nt = 0; nt < 8; nt++)
                *(float2*)&Cs[(size_t)(r + h * 8) * LDC + ccol + nt * 8] =
                    make_float2(e0[nt], e1[nt]);
        }
    }
    __syncthreads();
    if (tid < 128) {
        int l = l0 + tid;
        if (l < L) {
            size_t p = ((size_t)bb * L + l) * NST + st;
            g_pm[p] = srow[tid];
            g_pz[p] = spz[tid] + spz[128 + tid] + spz[256 + tid] + spz[384 + tid];
        }
    }
#pragma unroll
    for (int t = 0; t < 16; t++) {
        int idx = t * 512 + tid;
        int row = idx >> 6, c4 = idx & 63;
        int l = l0 + row;
        if (l < L)
            *(float4*)(ev + ((size_t)bb * L + l) * S + s0 + c4 * 4) =
                *(const float4*)&Cs[(size_t)row * LDC + c4 * 4];
    }
}

// ---------------- K2: reduce stats -> per-tile alpha scales -----------------
__global__ void k_reduce() {
    int idx = blockIdx.x * blockDim.x + threadIdx.x;
    if (idx >= B * L) return;
    const float* pm = g_pm + (size_t)idx * NST;
    const float* pz = g_pz + (size_t)idx * NST;
    float M = -3.4e38f;
#pragma unroll
    for (int t = 0; t < NST; t++) M = fmaxf(M, pm[t]);
    float Z = 0.f;
#pragma unroll
    for (int t = 0; t < NST; t++) Z += pz[t] * ex2f(pm[t] - M);
    float Zi = 1.0f / Z;
#pragma unroll
    for (int t = 0; t < NST; t++)
        g_sf[(size_t)idx * NST + t] = ex2f(pm[t] - M) * Zi;
}

// ---------------- K3: alpha = e*sf (no exp) + out = alpha @ x ---------------
__global__ void __launch_bounds__(512) k3(float* __restrict__ alpha,
                                          float* __restrict__ out)
{
    extern __shared__ __align__(128) char smem[];
    const uint32_t sb = smem_u32(smem);
    const int tid = threadIdx.x, lane = tid & 31, warp = tid >> 5;
    const int wm = warp & 3, wn = warp >> 2;
    const int bb = blockIdx.y, lt = blockIdx.x, l0 = lt * 128;
    const MmaCtx cx = make_ctx(warp, lane);

    float* sfs = (float*)(smem + SFS3);   // [128][16]
#pragma unroll
    for (int t = 0; t < 4; t++) {
        int idx = t * 512 + tid;
        int r = idx >> 4, tt = idx & 15;
        int l = l0 + r;
        sfs[idx] = (l < L) ? g_sf[((size_t)bb * L + l) * NST + tt] : 0.f;
    }
    if (tid == 0) { mbar_init(sb + MB3, 1); mbar_init(sb + MB3 + 8, 1); }
    __syncthreads();

    float acc[2][8][4];
#pragma unroll
    for (int i = 0; i < 2; i++)
#pragma unroll
        for (int j = 0; j < 8; j++)
#pragma unroll
            for (int k = 0; k < 4; k++) acc[i][j][k] = 0.f;

    auto issue_b = [&](int c) {
        const uint32_t mb   = sb + MB3 + (c & 1) * 8;
        const uint32_t base = sb + (c & 1) * STAGE3;
        const int sc = c * 64;
        if (tid == 0) mbar_arrive_tx(mb, 512u * 128u);
        if (tid < 256)
            bulk_cp(base + S3_BH + tid * PITCH,
                    gVh + ((size_t)bb * D + tid) * S + sc, 128, mb);
        else {
            int r = tid - 256;
            bulk_cp(base + S3_BL + r * PITCH,
                    gVl + ((size_t)bb * D + r) * S + sc, 128, mb);
        }
    };
    // alpha path: read e_val, scale by sf, write alpha, stage fp16 into smem A
    auto stage_a = [&](int c) {
        const uint32_t base = (uint32_t)((c & 1) * STAGE3);
        const int sc = c * 64;
        const int tile = c >> 2;          // 64*c / 256
#pragma unroll
        for (int t = 0; t < 4; t++) {
            int idx = t * 512 + tid;
            int r = idx >> 4, c4 = idx & 15;
            int l = l0 + r;
            float4 a;
            if (l < L) {
                float* ap = alpha + ((size_t)bb * L + l) * S + sc + c4 * 4;
                float4 e = *(const float4*)ap;
                float sf = sfs[r * 16 + tile];
                a.x = e.x * sf; a.y = e.y * sf; a.z = e.z * sf; a.w = e.w * sf;
                *(float4*)ap = a;
            } else a = make_float4(0.f, 0.f, 0.f, 0.f);
            *(uint2*)(smem + base + S3_A + r * PITCH + c4 * 8) =
                make_uint2(packh2(a.x, a.y), packh2(a.z, a.w));
        }
    };

    issue_b(0); stage_a(0);
    issue_b(1); stage_a(1);
    __syncthreads();

    constexpr int NC = 64;
    for (int c = 0; c < NC; c++) {
        mbar_wait(sb + MB3 + (c & 1) * 8, (c >> 1) & 1);
        tile_mma3(sb + (c & 1) * STAGE3, cx, acc);
        __syncthreads();
        if (c + 2 < NC) { stage_a(c + 2); issue_b(c + 2); }
    }

    // ---- epilogue: stage C, coalesced out stores ----
    __syncthreads();
    float* Cs = (float*)smem;   // [128][LDC]
#pragma unroll
    for (int mt = 0; mt < 2; mt++) {
        const int r = wm * 32 + mt * 16 + (lane >> 2);
        const int ccol = wn * 64 + (lane & 3) * 2;
#pragma unroll
        for (int nt = 0; nt < 8; nt++) {
            *(float2*)&Cs[(size_t)r * LDC + ccol + nt * 8] =
                make_float2(acc[mt][nt][0], acc[mt][nt][1]);
            *(float2*)&Cs[(size_t)(r + 8) * LDC + ccol + nt * 8] =
                make_float2(acc[mt][nt][2], acc[mt][nt][3]);
        }
    }
    __syncthreads();
#pragma unroll
    for (int t = 0; t < 16; t++) {
        int idx = t * 512 + tid;
        int row = idx >> 6, c4 = idx & 63;
        int l = l0 + row;
        if (l < L)
            *(float4*)(out + ((size_t)bb * L + l) * D + c4 * 4) =
                *(const float4*)&Cs[(size_t)row * LDC + c4 * 4];
    }
}

// ---------------------------------------------------------------------------
extern "C" void kernel_launch(void* const* d_in, const int* in_sizes, int n_in,
                              void* d_out, int out_size)
{
    const float* x = (const float*)d_in[0];   // [B,S,D]
    const float* U = (const float*)d_in[1];   // [L,D]

    float* out_ptr   = (float*)d_out;                      // [B,L,D]
    float* alpha_ptr = (float*)d_out + (size_t)B * L * D;  // [B,L,S]

    cudaFuncSetAttribute(k1, cudaFuncAttributeMaxDynamicSharedMemorySize, SMEM1);
    cudaFuncSetAttribute(k3, cudaFuncAttributeMaxDynamicSharedMemorySize, SMEM3);

    k_split_u<<<(L * D / 4 + 255) / 256, 256>>>(U);
    k_tsplit<<<dim3(S / 32, D / 32, B), dim3(32, 8)>>>(x);

    k1<<<dim3(NST, NLT, B), 512, SMEM1>>>(alpha_ptr);   // writes e_val

    k_reduce<<<(B * L + 255) / 256, 256>>>();

    k3<<<dim3(NLT, B), 512, SMEM3>>>(alpha_ptr, out_ptr);
}

// round 16
// speedup vs baseline: 1.2646x; 1.2646x over previous
#include <cuda_runtime.h>
#include <cuda_bf16.h>
#include <cuda_fp16.h>
#include <cstdint>

constexpr int B = 4;
constexpr int S = 4096;
constexpr int D = 256;
constexpr int L = 8921;

constexpr int NST = 16;     // S/256 s-tiles in K1
constexpr int NLT = 70;     // ceil(L/128)

// ---------------- device scratch ------------------------------------------
__device__ float g_pm[(size_t)B * L * NST];
__device__ float g_pz[(size_t)B * L * NST];
__device__ float g_sf[(size_t)B * L * NST];   // per-(row,tile) alpha scale

__device__ __nv_bfloat16 gUh[(size_t)L * D];      // U*log2e hi
__device__ __nv_bfloat16 gUl[(size_t)L * D];      // U*log2e lo
__device__ __nv_bfloat16 gXh[(size_t)B * S * D];
__device__ __nv_bfloat16 gXl[(size_t)B * S * D];
__device__ __half        gVh[(size_t)B * D * S];  // x^T fp16 hi

// ---------------- helpers --------------------------------------------------
__device__ __forceinline__ uint32_t smem_u32(const void* p) {
    uint32_t a;
    asm("{ .reg .u64 t; cvta.to.shared.u64 t, %1; cvt.u32.u64 %0, t; }" : "=r"(a) : "l"(p));
    return a;
}
__device__ __forceinline__ void cp16(uint32_t d, const void* s, uint32_t sz) {
    asm volatile("cp.async.cg.shared.global [%0], [%1], 16, %2;"
                 :: "r"(d), "l"(s), "r"(sz) : "memory");
}
__device__ __forceinline__ void cp_commit() {
    asm volatile("cp.async.commit_group;" ::: "memory");
}
template<int N> __device__ __forceinline__ void cp_wait() {
    asm volatile("cp.async.wait_group %0;" :: "n"(N) : "memory");
}
__device__ __forceinline__ void ldsm4(uint32_t* r, uint32_t a) {
    asm volatile("ldmatrix.sync.aligned.m8n8.x4.shared.b16 {%0,%1,%2,%3}, [%4];"
                 : "=r"(r[0]), "=r"(r[1]), "=r"(r[2]), "=r"(r[3]) : "r"(a));
}
__device__ __forceinline__ void mma_bf16(float* d, const uint32_t* a, uint32_t b0, uint32_t b1) {
    asm volatile("mma.sync.aligned.m16n8k16.row.col.f32.bf16.bf16.f32 "
                 "{%0,%1,%2,%3}, {%4,%5,%6,%7}, {%8,%9}, {%0,%1,%2,%3};"
                 : "+f"(d[0]), "+f"(d[1]), "+f"(d[2]), "+f"(d[3])
                 : "r"(a[0]), "r"(a[1]), "r"(a[2]), "r"(a[3]), "r"(b0), "r"(b1));
}
__device__ __forceinline__ void mma_f16(float* d, const uint32_t* a, uint32_t b0, uint32_t b1) {
    asm volatile("mma.sync.aligned.m16n8k16.row.col.f32.f16.f16.f32 "
                 "{%0,%1,%2,%3}, {%4,%5,%6,%7}, {%8,%9}, {%0,%1,%2,%3};"
                 : "+f"(d[0]), "+f"(d[1]), "+f"(d[2]), "+f"(d[3])
                 : "r"(a[0]), "r"(a[1]), "r"(a[2]), "r"(a[3]), "r"(b0), "r"(b1));
}
__device__ __forceinline__ float ex2f(float x) {
    float y;
    asm("ex2.approx.f32 %0, %1;" : "=f"(y) : "f"(x));
    return y;
}
__device__ __forceinline__ void split1(float v, __nv_bfloat16& h, __nv_bfloat16& l) {
    h = __float2bfloat16(v);
    l = __float2bfloat16(v - __bfloat162float(h));
}
__device__ __forceinline__ uint32_t pack2(__nv_bfloat16 a, __nv_bfloat16 b) {
    __nv_bfloat162 t = __halves2bfloat162(a, b);
    return *reinterpret_cast<uint32_t*>(&t);
}
__device__ __forceinline__ uint32_t packh2(float a, float b) {
    __half2 t = __floats2half2_rn(a, b);
    return *reinterpret_cast<uint32_t*>(&t);
}

// ---------------- smem layouts ----------------------------------------------
// k-chunk 32, rows padded to 80B (16B-aligned, ldsm conflict-free)
constexpr int PITCH  = 80;
// K1 (identical to R13)
constexpr int ST_AH  = 0;          // A hi: 128 rows * 80B
constexpr int ST_AL  = 10240;      // A lo
constexpr int ST_BH  = 20480;      // B hi: 256 rows * 80B
constexpr int ST_BL  = 40960;      // B lo
constexpr int STAGE  = 61440;
constexpr int HDR    = 6144;
constexpr int SMEM1  = HDR + 3 * STAGE;    // 190464

// K3: A alpha fp16 (128 rows), B x^T fp16 hi only (256 rows)
constexpr int S3_A   = 0;                   // 128*80 = 10240
constexpr int S3_BH  = 10240;               // 256*80 = 20480
constexpr int STAGE3 = 30720;
constexpr int SFS3   = 3 * STAGE3;          // 92160
constexpr int SMEM3  = SFS3 + 8192;         // 100352

constexpr int LDC = 264;           // K1 epilogue staging row stride

// ---------------- precompute kernels ---------------------------------------
__global__ void k_split_u(const float* __restrict__ src) {
    int i = blockIdx.x * blockDim.x + threadIdx.x;
    if (i >= L * D / 4) return;
    float4 v = ((const float4*)src)[i];
    const float LOG2E = 1.4426950408889634f;
    v.x *= LOG2E; v.y *= LOG2E; v.z *= LOG2E; v.w *= LOG2E;
    __nv_bfloat16 h0,h1,h2,h3,l0,l1,l2,l3;
    split1(v.x,h0,l0); split1(v.y,h1,l1); split1(v.z,h2,l2); split1(v.w,h3,l3);
    ((uint2*)gUh)[i] = make_uint2(pack2(h0,h1), pack2(h2,h3));
    ((uint2*)gUl)[i] = make_uint2(pack2(l0,l1), pack2(l2,l3));
}
// one pass over x: bf16 split (natural, K1) + fp16 hi (transposed, K3)
__global__ void k_tsplit(const float* __restrict__ x) {
    __shared__ float t[32][33];
    int b = blockIdx.z, s0 = blockIdx.x * 32, d0 = blockIdx.y * 32;
    int tx = threadIdx.x, ty = threadIdx.y;
    const float* xb = x + (size_t)b * S * D;
#pragma unroll
    for (int i = 0; i < 32; i += 8) {
        float v = xb[(size_t)(s0 + ty + i) * D + d0 + tx];
        t[ty + i][tx] = v;
        __nv_bfloat16 h, l; split1(v, h, l);
        size_t o = ((size_t)b * S + s0 + ty + i) * D + d0 + tx;
        gXh[o] = h; gXl[o] = l;
    }
    __syncthreads();
#pragma unroll
    for (int i = 0; i < 32; i += 8) {
        int dr = ty + i;
        float v = t[tx][dr];
        size_t o = ((size_t)b * D + d0 + dr) * S + s0 + tx;
        gVh[o] = __float2half(v);
    }
}

// ---------------- MMA ctx ----------------------------------------------------
struct MmaCtx { uint32_t arow, brow; };
__device__ __forceinline__ MmaCtx make_ctx(int warp, int lane) {
    int wm = warp & 3, wn = warp >> 2;
    MmaCtx c;
    c.arow = (uint32_t)((wm * 32 + (lane & 15)) * PITCH + (lane >> 4) * 16);
    c.brow = (uint32_t)((wn * 64 + (lane & 7) + ((lane >> 4) & 1) * 8) * PITCH
                        + ((lane >> 3) & 1) * 16);
    return c;
}

// K1 body: bf16 3-term, term-outermost (R13)
__device__ __forceinline__ void tile_mma(uint32_t base, const MmaCtx& cx,
                                         float (&acc)[2][8][4])
{
#pragma unroll
    for (int ks = 0; ks < 2; ks++) {
        uint32_t Ah[2][4], Al[2][4];
#pragma unroll
        for (int mt = 0; mt < 2; mt++) {
            ldsm4(Ah[mt], base + ST_AH + cx.arow + mt * (16 * PITCH) + ks * 32);
            ldsm4(Al[mt], base + ST_AL + cx.arow + mt * (16 * PITCH) + ks * 32);
        }
#pragma unroll
        for (int nph = 0; nph < 2; nph++) {
            uint32_t Bh[2][4], Bl[2][4];
#pragma unroll
            for (int j = 0; j < 2; j++) {
                int np = nph * 2 + j;
                ldsm4(Bh[j], base + ST_BH + cx.brow + np * (16 * PITCH) + ks * 32);
                ldsm4(Bl[j], base + ST_BL + cx.brow + np * (16 * PITCH) + ks * 32);
            }
#pragma unroll
            for (int j = 0; j < 2; j++) {
                int np = nph * 2 + j;
#pragma unroll
                for (int mt = 0; mt < 2; mt++) {
                    mma_bf16(acc[mt][np*2],   Ah[mt], Bh[j][0], Bh[j][1]);
                    mma_bf16(acc[mt][np*2+1], Ah[mt], Bh[j][2], Bh[j][3]);
                }
            }
#pragma unroll
            for (int j = 0; j < 2; j++) {
                int np = nph * 2 + j;
#pragma unroll
                for (int mt = 0; mt < 2; mt++) {
                    mma_bf16(acc[mt][np*2],   Ah[mt], Bl[j][0], Bl[j][1]);
                    mma_bf16(acc[mt][np*2+1], Ah[mt], Bl[j][2], Bl[j][3]);
                }
            }
#pragma unroll
            for (int j = 0; j < 2; j++) {
                int np = nph * 2 + j;
#pragma unroll
                for (int mt = 0; mt < 2; mt++) {
                    mma_bf16(acc[mt][np*2],   Al[mt], Bh[j][0], Bh[j][1]);
                    mma_bf16(acc[mt][np*2+1], Al[mt], Bh[j][2], Bh[j][3]);
                }
            }
        }
    }
}

// K3 body: fp16 single-term (alpha_h * x_h)
__device__ __forceinline__ void tile_mma3(uint32_t base, const MmaCtx& cx,
                                          float (&acc)[2][8][4])
{
#pragma unroll
    for (int ks = 0; ks < 2; ks++) {
        uint32_t Ah[2][4];
#pragma unroll
        for (int mt = 0; mt < 2; mt++)
            ldsm4(Ah[mt], base + S3_A + cx.arow + mt * (16 * PITCH) + ks * 32);
#pragma unroll
        for (int np = 0; np < 4; np++) {
            uint32_t Bh[4];
            ldsm4(Bh, base + S3_BH + cx.brow + np * (16 * PITCH) + ks * 32);
#pragma unroll
            for (int mt = 0; mt < 2; mt++) {
                mma_f16(acc[mt][np*2],   Ah[mt], Bh[0], Bh[1]);
                mma_f16(acc[mt][np*2+1], Ah[mt], Bh[2], Bh[3]);
            }
        }
    }
}

// ---------------- K1: e-values + per-tile stats (R13 staging) ---------------
__global__ void __launch_bounds__(512) k1(float* __restrict__ ev)
{
    extern __shared__ __align__(128) char smem[];
    const uint32_t sb = smem_u32(smem);
    const int tid = threadIdx.x, lane = tid & 31, warp = tid >> 5;
    const int wm = warp & 3, wn = warp >> 2;
    const int bb = blockIdx.z, lt = blockIdx.y, st = blockIdx.x;
    const int l0 = lt * 128, s0 = st * 256;
    const MmaCtx cx = make_ctx(warp, lane);

    float acc[2][8][4];
#pragma unroll
    for (int i = 0; i < 2; i++)
#pragma unroll
        for (int j = 0; j < 8; j++)
#pragma unroll
            for (int k = 0; k < 4; k++) acc[i][j][k] = 0.f;

    auto stage_c = [&](int c) {
        uint32_t base = sb + HDR + (c % 3) * STAGE;
        int kc = c * 32;
        {
            int r = tid >> 2, c16 = tid & 3;
            int l = l0 + r;
            int lc = l < L ? l : L - 1;
            uint32_t sz = (l < L) ? 16u : 0u;
            size_t g = (size_t)lc * D + kc + c16 * 8;
            uint32_t so = r * PITCH + c16 * 16;
            cp16(base + ST_AH + so, gUh + g, sz);
            cp16(base + ST_AL + so, gUl + g, sz);
        }
#pragma unroll
        for (int t = 0; t < 2; t++) {
            int idx = t * 512 + tid;
            int r = idx >> 2, c16 = idx & 3;
            size_t g = ((size_t)bb * S + s0 + r) * D + kc + c16 * 8;
            uint32_t so = r * PITCH + c16 * 16;
            cp16(base + ST_BH + so, gXh + g, 16);
            cp16(base + ST_BL + so, gXl + g, 16);
        }
        cp_commit();
    };

    stage_c(0);
    stage_c(1);

    constexpr int NC = 8;
    for (int c = 0; c < NC; c++) {
        if (c < NC - 1) cp_wait<1>(); else cp_wait<0>();
        __syncthreads();
        if (c + 2 < NC) stage_c(c + 2);
        tile_mma(sb + HDR + (c % 3) * STAGE, cx, acc);
    }

    // ---- epilogue (log2 domain): tile max, e-values, z, e-stores ----
    float* spmax = (float*)smem;          // [4][128]
    float* spz   = spmax + 512;           // [4][128]
    float* srow  = spz + 512;             // [128]
    float* Cs    = (float*)(smem + HDR);  // [128][LDC]
    const int rbase = wm * 32 + (lane >> 2);

#pragma unroll
    for (int mt = 0; mt < 2; mt++)
#pragma unroll
        for (int h = 0; h < 2; h++) {
            float m = -3.4e38f;
#pragma unroll
            for (int nt = 0; nt < 8; nt++)
                m = fmaxf(m, fmaxf(acc[mt][nt][h*2], acc[mt][nt][h*2+1]));
            m = fmaxf(m, __shfl_xor_sync(0xffffffffu, m, 1));
            m = fmaxf(m, __shfl_xor_sync(0xffffffffu, m, 2));
            if ((lane & 3) == 0)
                spmax[wn * 128 + rbase + mt * 16 + h * 8] = m;
        }
    __syncthreads();
    if (tid < 128) {
        float m = fmaxf(fmaxf(spmax[tid], spmax[128 + tid]),
                        fmaxf(spmax[256 + tid], spmax[384 + tid]));
        srow[tid] = m;
    }
    __syncthreads();
#pragma unroll
    for (int mt = 0; mt < 2; mt++) {
        const int r = wm * 32 + mt * 16 + (lane >> 2);
        const int ccol = wn * 64 + (lane & 3) * 2;
#pragma unroll
        for (int h = 0; h < 2; h++) {
            float M = srow[rbase + mt * 16 + h * 8];
            float z = 0.f;
            float e0[8], e1[8];
#pragma unroll
            for (int nt = 0; nt < 8; nt++) {
                e0[nt] = ex2f(acc[mt][nt][h*2]     - M);
                e1[nt] = ex2f(acc[mt][nt][h*2 + 1] - M);
                z += e0[nt] + e1[nt];
            }
            z += __shfl_xor_sync(0xffffffffu, z, 1);
            z += __shfl_xor_sync(0xffffffffu, z, 2);
            if ((lane & 3) == 0)
                spz[wn * 128 + rbase + mt * 16 + h * 8] = z;
#pragma unroll
            for (int nt = 0; nt < 8; nt++)
                *(float2*)&Cs[(size_t)(r + h * 8) * LDC + ccol + nt * 8] =
                    make_float2(e0[nt], e1[nt]);
        }
    }
    __syncthreads();
    if (tid < 128) {
        int l = l0 + tid;
        if (l < L) {
            size_t p = ((size_t)bb * L + l) * NST + st;
            g_pm[p] = srow[tid];
            g_pz[p] = spz[tid] + spz[128 + tid] + spz[256 + tid] + spz[384 + tid];
        }
    }
#pragma unroll
    for (int t = 0; t < 16; t++) {
        int idx = t * 512 + tid;
        int row = idx >> 6, c4 = idx & 63;
        int l = l0 + row;
        if (l < L)
            *(float4*)(ev + ((size_t)bb * L + l) * S + s0 + c4 * 4) =
                *(const float4*)&Cs[(size_t)row * LDC + c4 * 4];
    }
}

// ---------------- K2: reduce stats -> per-tile alpha scales -----------------
__global__ void k_reduce() {
    int idx = blockIdx.x * blockDim.x + threadIdx.x;
    if (idx >= B * L) return;
    const float* pm = g_pm + (size_t)idx * NST;
    const float* pz = g_pz + (size_t)idx * NST;
    float M = -3.4e38f;
#pragma unroll
    for (int t = 0; t < NST; t++) M = fmaxf(M, pm[t]);
    float Z = 0.f;
#pragma unroll
    for (int t = 0; t < NST; t++) Z += pz[t] * ex2f(pm[t] - M);
    float Zi = 1.0f / Z;
#pragma unroll
    for (int t = 0; t < NST; t++)
        g_sf[(size_t)idx * NST + t] = ex2f(pm[t] - M) * Zi;
}

// ---------------- K3: alpha = e*sf + out = alpha_h @ x_h --------------------
__global__ void __launch_bounds__(512) k3(float* __restrict__ alpha,
                                          float* __restrict__ out)
{
    extern __shared__ __align__(128) char smem[];
    const uint32_t sb = smem_u32(smem);
    const int tid = threadIdx.x, lane = tid & 31, warp = tid >> 5;
    const int wm = warp & 3, wn = warp >> 2;
    const int bb = blockIdx.y, lt = blockIdx.x, l0 = lt * 128;
    const MmaCtx cx = make_ctx(warp, lane);

    float* sfs = (float*)(smem + SFS3);   // [128][16]
#pragma unroll
    for (int t = 0; t < 4; t++) {
        int idx = t * 512 + tid;
        int r = idx >> 4, tt = idx & 15;
        int l = l0 + r;
        sfs[idx] = (l < L) ? g_sf[((size_t)bb * L + l) * NST + tt] : 0.f;
    }
    __syncthreads();

    float acc[2][8][4];
#pragma unroll
    for (int i = 0; i < 2; i++)
#pragma unroll
        for (int j = 0; j < 8; j++)
#pragma unroll
            for (int k = 0; k < 4; k++) acc[i][j][k] = 0.f;

    const int ar = tid >> 3, ac = tid & 7;   // A rows ar, ar+64; float4-col ac

    auto stage_b = [&](int c) {
        uint32_t base = sb + (c % 3) * STAGE3;
        int s0 = c * 32;
#pragma unroll
        for (int t = 0; t < 2; t++) {
            int idx = t * 512 + tid;
            int r = idx >> 2, c16 = idx & 3;
            size_t g = ((size_t)bb * D + r) * S + s0 + c16 * 8;
            cp16(base + S3_BH + r * PITCH + c16 * 16, gVh + g, 16);
        }
        cp_commit();
    };
    auto a_load = [&](int c, float4* v) {
        int s0 = c * 32;
#pragma unroll
        for (int t = 0; t < 2; t++) {
            int l = l0 + ar + t * 64;
            v[t] = (l < L)
                 ? *(const float4*)(alpha + ((size_t)bb * L + l) * S + s0 + ac * 4)
                 : make_float4(0,0,0,0);
        }
    };
    auto a_store = [&](int c, const float4* v) {
        int s0 = c * 32;
        uint32_t base = (uint32_t)((c % 3) * STAGE3);
        const int tile = c >> 3;   // (c*32)/256
#pragma unroll
        for (int t = 0; t < 2; t++) {
            int r = ar + t * 64;
            int l = l0 + r;
            float4 a = v[t];
            float sf = sfs[r * 16 + tile];
            a.x *= sf; a.y *= sf; a.z *= sf; a.w *= sf;
            if (l >= L) a = make_float4(0,0,0,0);
            else
                *(float4*)(alpha + ((size_t)bb * L + l) * S + s0 + ac * 4) = a;
            *(uint2*)(smem + base + S3_A + r * PITCH + ac * 8) =
                make_uint2(packh2(a.x, a.y), packh2(a.z, a.w));
        }
    };

    float4 v0[2], v1[2];
    stage_b(0); a_load(0, v0); a_store(0, v0);
    stage_b(1); a_load(1, v1); a_store(1, v1);

    constexpr int NC = 128;
    float4 vp[2];
    for (int c = 0; c < NC; c++) {
        if (c < NC - 1) cp_wait<1>(); else cp_wait<0>();
        __syncthreads();
        bool pf = (c + 2 < NC);
        if (pf) { stage_b(c + 2); a_load(c + 2, vp); }
        tile_mma3(sb + (c % 3) * STAGE3, cx, acc);
        if (pf) a_store(c + 2, vp);
    }

    // ---- epilogue: scatter out stores (measured cost-neutral) ----
#pragma unroll
    for (int mt = 0; mt < 2; mt++) {
        int r0 = l0 + wm * 32 + mt * 16 + (lane >> 2);
#pragma unroll
        for (int nt = 0; nt < 8; nt++) {
            int col = wn * 64 + nt * 8 + (lane & 3) * 2;
            if (r0 < L)
                *(float2*)(out + ((size_t)bb * L + r0) * D + col) =
                    make_float2(acc[mt][nt][0], acc[mt][nt][1]);
            if (r0 + 8 < L)
                *(float2*)(out + ((size_t)bb * L + r0 + 8) * D + col) =
                    make_float2(acc[mt][nt][2], acc[mt][nt][3]);
        }
    }
}

// ---------------------------------------------------------------------------
extern "C" void kernel_launch(void* const* d_in, const int* in_sizes, int n_in,
                              void* d_out, int out_size)
{
    const float* x = (const float*)d_in[0];   // [B,S,D]
    const float* U = (const float*)d_in[1];   // [L,D]

    float* out_ptr   = (float*)d_out;                      // [B,L,D]
    float* alpha_ptr = (float*)d_out + (size_t)B * L * D;  // [B,L,S]

    cudaFuncSetAttribute(k1, cudaFuncAttributeMaxDynamicSharedMemorySize, SMEM1);
    cudaFuncSetAttribute(k3, cudaFuncAttributeMaxDynamicSharedMemorySize, SMEM3);

    k_split_u<<<(L * D / 4 + 255) / 256, 256>>>(U);
    k_tsplit<<<dim3(S / 32, D / 32, B), dim3(32, 8)>>>(x);

    k1<<<dim3(NST, NLT, B), 512, SMEM1>>>(alpha_ptr);   // writes e-values

    k_reduce<<<(B * L + 255) / 256, 256>>>();

    k3<<<dim3(NLT, B), 512, SMEM3>>>(alpha_ptr, out_ptr);
}